// round 1
// baseline (speedup 1.0000x reference)
#include <cuda_runtime.h>

// Problem shape (fixed by the reference): inputs [B=8, T=4096, C=1024] fp32.
// out[b, t, c] = (1/(t+1)) * sum_{s<=t} in[b, s, c]
//
// Strategy: partitioned scan over T.
//   K1: per-(b, seg, c) segment sums  -> g_partials[b][seg][c]
//   K2: tiny serial exclusive scan over the 32 segments per column (in-place)
//   K3: re-read input, add carry-in, multiply by reciprocal(t+1), write out.
// All loads/stores coalesced along c (innermost dim). 1024 CTAs per big kernel.

#define B_DIM 8
#define T_DIM 4096
#define C_DIM 1024
#define NSEG 32
#define SEGLEN (T_DIM / NSEG)   // 128
#define CT 256                  // threads per block == columns per c-tile
#define CTILES (C_DIM / CT)     // 4

// Scratch: 8 * 32 * 1024 floats = 1 MB. __device__ global (no allocation).
__device__ float g_partials[B_DIM * NSEG * C_DIM];

__global__ __launch_bounds__(CT) void seg_sum_kernel(const float* __restrict__ in) {
    const int c   = blockIdx.x * CT + threadIdx.x;
    const int seg = blockIdx.y;
    const int b   = blockIdx.z;

    const float* p = in + ((size_t)b * T_DIM + (size_t)seg * SEGLEN) * C_DIM + c;

    float s = 0.0f;
#pragma unroll 8
    for (int t = 0; t < SEGLEN; ++t) {
        s += p[(size_t)t * C_DIM];
    }
    g_partials[(b * NSEG + seg) * C_DIM + c] = s;
}

__global__ __launch_bounds__(256) void seg_scan_kernel() {
    // One thread per (b, c) column: serial exclusive scan over NSEG segments.
    const int col = blockIdx.x * blockDim.x + threadIdx.x;  // 0 .. B*C-1
    if (col >= B_DIM * C_DIM) return;
    const int b = col / C_DIM;
    const int c = col % C_DIM;

    float run = 0.0f;
#pragma unroll
    for (int s = 0; s < NSEG; ++s) {
        const int idx = (b * NSEG + s) * C_DIM + c;
        const float v = g_partials[idx];
        g_partials[idx] = run;   // exclusive prefix
        run += v;
    }
}

__global__ __launch_bounds__(CT) void seg_out_kernel(const float* __restrict__ in,
                                                     float* __restrict__ out) {
    const int c   = blockIdx.x * CT + threadIdx.x;
    const int seg = blockIdx.y;
    const int b   = blockIdx.z;
    const int t0  = seg * SEGLEN;

    const size_t base = ((size_t)b * T_DIM + t0) * C_DIM + c;
    float carry = g_partials[(b * NSEG + seg) * C_DIM + c];

#pragma unroll 4
    for (int t = 0; t < SEGLEN; ++t) {
        carry += in[base + (size_t)t * C_DIM];
        // reciprocal-multiply instead of divide: ~1 ulp, far under 1e-3 tol
        out[base + (size_t)t * C_DIM] = carry * __frcp_rn((float)(t0 + t + 1));
    }
}

extern "C" void kernel_launch(void* const* d_in, const int* in_sizes, int n_in,
                              void* d_out, int out_size) {
    (void)in_sizes; (void)n_in; (void)out_size;
    const float* in = (const float*)d_in[0];
    float* out = (float*)d_out;

    dim3 big_grid(CTILES, NSEG, B_DIM);   // 4 x 32 x 8 = 1024 CTAs
    seg_sum_kernel<<<big_grid, CT>>>(in);

    seg_scan_kernel<<<(B_DIM * C_DIM + 255) / 256, 256>>>();

    seg_out_kernel<<<big_grid, CT>>>(in, out);
}

// round 7
// speedup vs baseline: 1.5060x; 1.5060x over previous
#include <cuda_runtime.h>

// inputs [B=8, T=4096, C=1024] fp32 -> out[b,t,c] = mean over s<=t of in[b,s,c]
//
// Two-pass partitioned scan (no inter-CTA waiting -> guaranteed termination):
//   K1: per-(b,seg) segment sums over SEGLEN rows -> g_partials  (reads input once)
//   K3: prelude sums predecessor segment sums (exclusive carry), then re-reads
//       input, emits (carry + local prefix) * rcp(t+1).
// All traffic float4-vectorized; one CTA covers the full 1024-column row.
// Reciprocals come from a 64-entry smem table (kills the old MUFU bottleneck).

#define B_DIM   8
#define T_DIM   4096
#define C_DIM   1024
#define CT      256                   // threads; each owns 4 consecutive columns
#define SEGLEN  64
#define NSEG    (T_DIM / SEGLEN)      // 64

// 8 * 64 * 1024 * 4 B = 2 MB scratch; __device__ global (no allocations).
__device__ float4 g_partials[B_DIM * NSEG * (C_DIM / 4)];

__global__ __launch_bounds__(CT) void seg_sum_kernel(const float* __restrict__ in) {
    const int seg = blockIdx.x;
    const int b   = blockIdx.y;

    const float4* p = reinterpret_cast<const float4*>(
        in + ((size_t)b * T_DIM + (size_t)seg * SEGLEN) * C_DIM) + threadIdx.x;

    // Two accumulators per component -> 8 independent FADD chains, full MLP.
    float4 s0 = make_float4(0.f, 0.f, 0.f, 0.f);
    float4 s1 = make_float4(0.f, 0.f, 0.f, 0.f);
#pragma unroll 8
    for (int t = 0; t < SEGLEN; t += 2) {
        const float4 a = p[(size_t)t * (C_DIM / 4)];
        const float4 c = p[(size_t)(t + 1) * (C_DIM / 4)];
        s0.x += a.x; s0.y += a.y; s0.z += a.z; s0.w += a.w;
        s1.x += c.x; s1.y += c.y; s1.z += c.z; s1.w += c.w;
    }
    s0.x += s1.x; s0.y += s1.y; s0.z += s1.z; s0.w += s1.w;

    g_partials[(b * NSEG + seg) * (C_DIM / 4) + threadIdx.x] = s0;
}

__global__ __launch_bounds__(CT) void scan_out_kernel(const float* __restrict__ in,
                                                      float* __restrict__ out) {
    const int seg = blockIdx.x;
    const int b   = blockIdx.y;
    const int t0  = seg * SEGLEN;

    __shared__ float s_rcp[SEGLEN];
    if (threadIdx.x < SEGLEN)
        s_rcp[threadIdx.x] = __frcp_rn((float)(t0 + threadIdx.x + 1));
    __syncthreads();

    // Exclusive carry: sum of segment aggregates for segs < seg (bounded loop,
    // <= 63 coalesced float4 loads; 0 for seg==0).
    float4 carry = make_float4(0.f, 0.f, 0.f, 0.f);
    for (int s = 0; s < seg; ++s) {
        const float4 a = g_partials[(b * NSEG + s) * (C_DIM / 4) + threadIdx.x];
        carry.x += a.x; carry.y += a.y; carry.z += a.z; carry.w += a.w;
    }

    const float4* pin = reinterpret_cast<const float4*>(
        in + ((size_t)b * T_DIM + t0) * C_DIM) + threadIdx.x;
    float4* pout = reinterpret_cast<float4*>(
        out + ((size_t)b * T_DIM + t0) * C_DIM) + threadIdx.x;

#pragma unroll 8
    for (int t = 0; t < SEGLEN; ++t) {
        const float4 a = pin[(size_t)t * (C_DIM / 4)];   // loads independent of carry
        carry.x += a.x; carry.y += a.y; carry.z += a.z; carry.w += a.w;
        const float r = s_rcp[t];                        // LDS broadcast
        float4 o;
        o.x = carry.x * r; o.y = carry.y * r; o.z = carry.z * r; o.w = carry.w * r;
        pout[(size_t)t * (C_DIM / 4)] = o;
    }
}

extern "C" void kernel_launch(void* const* d_in, const int* in_sizes, int n_in,
                              void* d_out, int out_size) {
    (void)in_sizes; (void)n_in; (void)out_size;
    const float* in = (const float*)d_in[0];
    float* out = (float*)d_out;

    dim3 grid(NSEG, B_DIM);                  // 64 x 8 = 512 CTAs per kernel
    seg_sum_kernel<<<grid, CT>>>(in);
    scan_out_kernel<<<grid, CT>>>(in, out);
}